// round 5
// baseline (speedup 1.0000x reference)
#include <cuda_runtime.h>
#include <cuda_bf16.h>
#include <cstdint>
#include <float.h>

#define BATCH 65536
#define DIM   512
#define KC    1024
#define NCLS  100
#define GAMMA 0.99f
#define EPSV  1e-5f

#define DK (DIM * KC)      // 524288
#define KCC (KC * NCLS)    // 102400

// ---------------- scratch (device globals) ----------------
__device__ float                 g_wsq[KC];
__device__ float                 g_counts[KC];
__device__ __align__(16) float   g_esum[KC * DIM];     // [K][D]
__device__ float                 g_bhist[KC * NCLS];
__device__ int                   g_argmin[BATCH];
__device__ float                 g_n;
__device__ __align__(16) __nv_bfloat16 g_wbf[DIM * KC];  // bf16 W, [D][K]
__device__ float                 g_wt32[KC * DIM];     // W^T fp32 [K][D] (rescue)
__device__ int                   g_rescue_cnt;
__device__ int                   g_r_row[BATCH];
__device__ int                   g_r_k[BATCH * 4];

// ---------------- PTX helpers (sm_100-base safe) ----------------
__device__ __forceinline__ uint32_t smem_u32(const void* p) {
    uint32_t a;
    asm("{ .reg .u64 t; cvta.to.shared.u64 t, %1; cvt.u32.u64 %0, t; }"
        : "=r"(a) : "l"(p));
    return a;
}
__device__ __forceinline__ void ldsm_x4(uint32_t* r, uint32_t addr) {
    asm volatile("ldmatrix.sync.aligned.m8n8.x4.shared.b16 {%0,%1,%2,%3}, [%4];"
                 : "=r"(r[0]), "=r"(r[1]), "=r"(r[2]), "=r"(r[3]) : "r"(addr));
}
__device__ __forceinline__ void ldsm_x4_t(uint32_t* r, uint32_t addr) {
    asm volatile("ldmatrix.sync.aligned.m8n8.x4.trans.shared.b16 {%0,%1,%2,%3}, [%4];"
                 : "=r"(r[0]), "=r"(r[1]), "=r"(r[2]), "=r"(r[3]) : "r"(addr));
}
__device__ __forceinline__ void mma16816(float* c, const uint32_t* a,
                                         uint32_t b0, uint32_t b1) {
    asm volatile("mma.sync.aligned.m16n8k16.row.col.f32.bf16.bf16.f32 "
                 "{%0,%1,%2,%3}, {%4,%5,%6,%7}, {%8,%9}, {%0,%1,%2,%3};"
                 : "+f"(c[0]), "+f"(c[1]), "+f"(c[2]), "+f"(c[3])
                 : "r"(a[0]), "r"(a[1]), "r"(a[2]), "r"(a[3]), "r"(b0), "r"(b1));
}
__device__ __forceinline__ void cp_async16(uint32_t dst, const void* src) {
    asm volatile("cp.async.cg.shared.global [%0], [%1], 16;"
                 :: "r"(dst), "l"(src) : "memory");
}
#define CP_COMMIT() asm volatile("cp.async.commit_group;" ::: "memory")
#define CP_WAIT2()  asm volatile("cp.async.wait_group 2;"  ::: "memory")
__device__ __forceinline__ uint32_t bf2u(float lo, float hi) {
    __nv_bfloat162 p = __floats2bfloat162_rn(lo, hi);
    return *reinterpret_cast<uint32_t*>(&p);
}

// ---------------------------------------------------------------
__global__ void zero_kernel() {
    int total = KC + KC * DIM + KC * NCLS;
    for (int i = blockIdx.x * blockDim.x + threadIdx.x; i < total;
         i += gridDim.x * blockDim.x) {
        if (i < KC) g_counts[i] = 0.0f;
        else if (i < KC + KC * DIM) g_esum[i - KC] = 0.0f;
        else g_bhist[i - KC - KC * DIM] = 0.0f;
    }
    if (blockIdx.x == 0 && threadIdx.x == 0) g_rescue_cnt = 0;
}

__global__ void wsq_kernel(const float* __restrict__ W) {
    int k = blockIdx.x * blockDim.x + threadIdx.x;
    if (k >= KC) return;
    float a = 0.0f;
    #pragma unroll 8
    for (int d = 0; d < DIM; d++) {
        float w = W[d * KC + k];
        a += w * w;
    }
    g_wsq[k] = a;
}

// Transpose W [D][K] -> W^T fp32 [K][D] (rescue) + write bf16 copy [D][K]
__global__ void wt_kernel(const float* __restrict__ W) {
    __shared__ float tile[32][33];
    int k0 = blockIdx.x * 32, d0 = blockIdx.y * 32;
    int tx = threadIdx.x, ty = threadIdx.y;   // (32, 8)
    #pragma unroll
    for (int j = 0; j < 4; j++) {
        size_t gi = (size_t)(d0 + ty + 8 * j) * KC + k0 + tx;
        float v = W[gi];
        tile[ty + 8 * j][tx] = v;
        g_wbf[gi] = __float2bfloat16_rn(v);
    }
    __syncthreads();
    #pragma unroll
    for (int j = 0; j < 4; j++)
        g_wt32[(size_t)(k0 + ty + 8 * j) * DIM + d0 + tx] = tile[tx][ty + 8 * j];
}

// ---------------------------------------------------------------
// mma.sync bf16 GEMM + top-k argmin.  512 threads (16 warps, 4m x 4n),
// 128 batch rows.  X tile resident in smem; B [64k][128n] in a 4-stage
// cp.async ring.  One __syncthreads per chunk.
// ---------------------------------------------------------------
#define SA_OFF   0                     // 131072: A [128][512] bf16
#define SB_OFF   131072                // 4 x 16384 B ring
#define WSQ_OFF  (SB_OFF + 65536)      // 196608, 4096 bytes
#define RED_OFF  SB_OFF                // reuse ring for merge: 128*16*16 = 32768
#define SM_TOTAL (WSQ_OFF + 4096)      // 200704
#define RESCUE_T 2.0f

__device__ __forceinline__ void load_b_chunk(uint32_t smb, int c, int tid) {
    int s = c & 3;
    int d0 = (c & 7) * 64, n0 = (c >> 3) * 128;
    #pragma unroll
    for (int t = 0; t < 2; t++) {
        int ul = t * 512 + tid;
        int kr = ul >> 4, u = ul & 15;
        cp_async16(smb + SB_OFF + s * 16384 + kr * 256 + ((u ^ (kr & 7)) * 16),
                   &g_wbf[(size_t)(d0 + kr) * KC + n0 + u * 8]);
    }
}

__global__ __launch_bounds__(512, 1)
void argmin_mma(const float* __restrict__ X, float* __restrict__ out_am) {
    extern __shared__ unsigned char sm[];
    uint32_t smb = smem_u32(sm);
    float*  s_wsq = (float*)(sm + WSQ_OFF);
    float4* red   = (float4*)(sm + RED_OFF);

    int tid  = threadIdx.x;
    int lane = tid & 31;
    int wid  = tid >> 5;
    int wm   = wid >> 2;        // 0..3 -> rows wm*32..+32
    int wn   = wid & 3;         // 0..3 -> cols wn*32..+32
    int row0 = blockIdx.x * 128;

    #pragma unroll
    for (int i = tid; i < KC; i += 512) s_wsq[i] = g_wsq[i];

    // ---- load X tile -> bf16 swizzled smem ----
    #pragma unroll
    for (int it = 0; it < 16; it++) {
        int ul = it * 512 + tid;        // 8192 16B units
        int r = ul >> 6, u = ul & 63;
        const float4* xp = reinterpret_cast<const float4*>(
            &X[(size_t)(row0 + r) * DIM + u * 8]);
        float4 f0 = xp[0], f1 = xp[1];
        uint4 q;
        q.x = bf2u(f0.x, f0.y); q.y = bf2u(f0.z, f0.w);
        q.z = bf2u(f1.x, f1.y); q.w = bf2u(f1.z, f1.w);
        *reinterpret_cast<uint4*>(sm + SA_OFF + r * 1024 + ((u ^ (r & 7)) * 16)) = q;
    }

    // prologue: stages 0..2
    load_b_chunk(smb, 0, tid); CP_COMMIT();
    load_b_chunk(smb, 1, tid); CP_COMMIT();
    load_b_chunk(smb, 2, tid); CP_COMMIT();

    float tv1[4], tv2[4];
    int   tk1[4], tk2[4];
    #pragma unroll
    for (int s = 0; s < 4; s++) { tv1[s] = FLT_MAX; tv2[s] = FLT_MAX; tk1[s] = KC; tk2[s] = KC; }

    int mrow = wm * 32 + (lane & 15);
    int hi   = lane >> 4;
    int mx   = mrow & 7;
    int kl   = lane & 15;
    int kx   = kl & 7;

    for (int nc = 0; nc < 8; nc++) {
        float acc[2][4][4];
        #pragma unroll
        for (int i = 0; i < 2; i++)
            #pragma unroll
            for (int j = 0; j < 4; j++)
                #pragma unroll
                for (int c = 0; c < 4; c++) acc[i][j][c] = 0.0f;

        for (int dc = 0; dc < 8; dc++) {
            int c = nc * 8 + dc;
            CP_WAIT2();
            __syncthreads();
            if (c + 3 < 64) load_b_chunk(smb, c + 3, tid);
            CP_COMMIT();                          // empty groups keep wait math exact
            uint32_t bbase = smb + SB_OFF + (c & 3) * 16384;
            #pragma unroll
            for (int ks = 0; ks < 4; ks++) {
                uint32_t a[2][4];
                #pragma unroll
                for (int i = 0; i < 2; i++)
                    ldsm_x4(a[i], smb + SA_OFF + (mrow + i * 16) * 1024 +
                                  (((dc * 8 + ks * 2 + hi) ^ mx) * 16));
                uint32_t bfr[2][4];
                #pragma unroll
                for (int jj = 0; jj < 2; jj++)
                    ldsm_x4_t(bfr[jj], bbase + (ks * 16 + kl) * 256 +
                                       (((wn * 4 + jj * 2 + hi) ^ kx) * 16));
                #pragma unroll
                for (int i = 0; i < 2; i++)
                    #pragma unroll
                    for (int jj = 0; jj < 2; jj++) {
                        mma16816(acc[i][jj * 2],     a[i], bfr[jj][0], bfr[jj][1]);
                        mma16816(acc[i][jj * 2 + 1], a[i], bfr[jj][2], bfr[jj][3]);
                    }
            }
        }

        // ---- epilogue: scores + running top-2 per row-slot ----
        int kbase = nc * 128 + wn * 32 + (lane & 3) * 2;
        #pragma unroll
        for (int i = 0; i < 2; i++)
            #pragma unroll
            for (int h = 0; h < 2; h++) {
                int slot = i * 2 + h;
                #pragma unroll
                for (int j = 0; j < 4; j++) {
                    int kg = kbase + j * 8;
                    float s0 = fmaf(-2.0f, acc[i][j][h * 2 + 0], s_wsq[kg]);
                    float s1 = fmaf(-2.0f, acc[i][j][h * 2 + 1], s_wsq[kg + 1]);
                    if (s0 < tv1[slot])      { tv2[slot] = tv1[slot]; tk2[slot] = tk1[slot]; tv1[slot] = s0; tk1[slot] = kg; }
                    else if (s0 < tv2[slot]) { tv2[slot] = s0; tk2[slot] = kg; }
                    if (s1 < tv1[slot])      { tv2[slot] = tv1[slot]; tk2[slot] = tk1[slot]; tv1[slot] = s1; tk1[slot] = kg + 1; }
                    else if (s1 < tv2[slot]) { tv2[slot] = s1; tk2[slot] = kg + 1; }
                }
            }
    }

    // ---- per-thread top-2 -> merge smem (overlaps B ring; GEMM done) ----
    __syncthreads();
    int ci = wn * 4 + (lane & 3);
    #pragma unroll
    for (int i = 0; i < 2; i++)
        #pragma unroll
        for (int h = 0; h < 2; h++) {
            int slot = i * 2 + h;
            int r = wm * 32 + i * 16 + h * 8 + (lane >> 2);
            float4 e;
            e.x = tv1[slot]; e.y = __int_as_float(tk1[slot]);
            e.z = tv2[slot]; e.w = __int_as_float(tk2[slot]);
            red[r * 16 + ci] = e;
        }
    __syncthreads();

    // ---- per-row merge: top-4 of 32 candidates, lexicographic (v, k) ----
    if (tid < 128) {
        float bv[4] = {FLT_MAX, FLT_MAX, FLT_MAX, FLT_MAX};
        int   bk[4] = {KC, KC, KC, KC};
        #pragma unroll
        for (int c = 0; c < 16; c++) {
            float4 e = red[tid * 16 + c];
            float cv[2] = {e.x, e.z};
            int   ck[2] = {__float_as_int(e.y), __float_as_int(e.w)};
            #pragma unroll
            for (int w = 0; w < 2; w++) {
                float v = cv[w]; int k = ck[w];
                if (v < bv[3] || (v == bv[3] && k < bk[3])) {
                    bv[3] = v; bk[3] = k;
                    if (bv[3] < bv[2] || (bv[3] == bv[2] && bk[3] < bk[2])) {
                        float t = bv[2]; bv[2] = bv[3]; bv[3] = t;
                        int ti = bk[2]; bk[2] = bk[3]; bk[3] = ti;
                    }
                    if (bv[2] < bv[1] || (bv[2] == bv[1] && bk[2] < bk[1])) {
                        float t = bv[1]; bv[1] = bv[2]; bv[2] = t;
                        int ti = bk[1]; bk[1] = bk[2]; bk[2] = ti;
                    }
                    if (bv[1] < bv[0] || (bv[1] == bv[0] && bk[1] < bk[0])) {
                        float t = bv[0]; bv[0] = bv[1]; bv[1] = t;
                        int ti = bk[0]; bk[0] = bk[1]; bk[1] = ti;
                    }
                }
            }
        }
        int b = row0 + tid;
        if (bv[1] - bv[0] > RESCUE_T) {
            g_argmin[b] = bk[0];
            out_am[b] = (float)bk[0];
        } else {
            int e = atomicAdd(&g_rescue_cnt, 1);
            g_r_row[e] = b;
            #pragma unroll
            for (int w = 0; w < 4; w++) g_r_k[e * 4 + w] = bk[w];
        }
    }
}

// ---------------------------------------------------------------
// Exact fp32 rescue: top-4 candidates per flagged row, one warp each.
// ---------------------------------------------------------------
__global__ void rescue_kernel(const float* __restrict__ X,
                              float* __restrict__ out_am) {
    int lane = threadIdx.x & 31;
    int warpGlobal = (blockIdx.x * blockDim.x + threadIdx.x) >> 5;
    int nWarps = (gridDim.x * blockDim.x) >> 5;
    int cnt = g_rescue_cnt;
    for (int e = warpGlobal; e < cnt; e += nWarps) {
        int b = g_r_row[e];
        int kk[4];
        #pragma unroll
        for (int w = 0; w < 4; w++) kk[w] = g_r_k[e * 4 + w];
        const float* xr = X + (size_t)b * DIM;
        float dot[4] = {0.0f, 0.0f, 0.0f, 0.0f};
        #pragma unroll 4
        for (int d = lane; d < DIM; d += 32) {
            float x = xr[d];
            #pragma unroll
            for (int w = 0; w < 4; w++)
                if (kk[w] < KC)
                    dot[w] += x * g_wt32[(size_t)kk[w] * DIM + d];
        }
        #pragma unroll
        for (int off = 16; off > 0; off >>= 1)
            #pragma unroll
            for (int w = 0; w < 4; w++)
                dot[w] += __shfl_xor_sync(0xffffffff, dot[w], off);
        if (lane == 0) {
            float bv = FLT_MAX; int bi = KC;
            #pragma unroll
            for (int w = 0; w < 4; w++) {
                if (kk[w] >= KC) continue;
                float s = g_wsq[kk[w]] - 2.0f * dot[w];
                if (s < bv || (s == bv && kk[w] < bi)) { bv = s; bi = kk[w]; }
            }
            g_argmin[b] = bi;
            out_am[b] = (float)bi;
        }
    }
}

// ---------------------------------------------------------------
// Scatter: counts, class histogram, embed_sum via vector red (sm_90+)
// ---------------------------------------------------------------
__global__ void scatter_kernel(const float* __restrict__ X,
                               const int* __restrict__ keys) {
    int b = blockIdx.x;
    int k = g_argmin[b];
    int t = threadIdx.x;   // 128 threads
    if (t == 0) {
        atomicAdd(&g_counts[k], 1.0f);
        atomicAdd(&g_bhist[k * NCLS + keys[b]], 1.0f);
    }
    float4 v = *reinterpret_cast<const float4*>(X + (size_t)b * DIM + t * 4);
    float* es = g_esum + (size_t)k * DIM + t * 4;
    asm volatile("red.global.add.v4.f32 [%0], {%1, %2, %3, %4};"
                 :: "l"(es), "f"(v.x), "f"(v.y), "f"(v.z), "f"(v.w) : "memory");
}

__global__ void fincs_kernel(const float* __restrict__ cs,
                             float* __restrict__ out_cs) {
    __shared__ float sred[KC];
    int k = threadIdx.x;
    float c = g_counts[k];
    if (c == 0.0f) c = 1.0f;
    float ncs = cs[k] * GAMMA + (1.0f - GAMMA) * c;
    out_cs[k] = ncs;
    sred[k] = ncs;
    __syncthreads();
    for (int s = KC / 2; s > 0; s >>= 1) {
        if (k < s) sred[k] += sred[k + s];
        __syncthreads();
    }
    if (k == 0) g_n = sred[0];
}

// finalize weight + embed_avg: tiled transpose of g_esum for coalescing
__global__ void finw_kernel(const float* __restrict__ ea,
                            const float* __restrict__ out_cs,
                            float* __restrict__ out_w,
                            float* __restrict__ out_ea) {
    __shared__ float tile[32][33];
    int k0 = blockIdx.x * 32, d0 = blockIdx.y * 32;
    int tx = threadIdx.x, ty = threadIdx.y;   // (32, 8)
    #pragma unroll
    for (int j = 0; j < 4; j++)
        tile[ty + 8 * j][tx] = g_esum[(size_t)(k0 + ty + 8 * j) * DIM + d0 + tx];
    __syncthreads();
    float n = g_n;
    float csn = (out_cs[k0 + tx] + EPSV) / (n + KC * EPSV) * n;
    #pragma unroll
    for (int j = 0; j < 4; j++) {
        size_t i = (size_t)(d0 + ty + 8 * j) * KC + k0 + tx;
        float e = ea[i] * GAMMA + (1.0f - GAMMA) * tile[tx][ty + 8 * j];
        out_ea[i] = e;
        out_w[i] = e / csn;
    }
}

__global__ void finh_kernel(const float* __restrict__ hist,
                            float* __restrict__ out_h) {
    int i = blockIdx.x * blockDim.x + threadIdx.x;
    if (i >= KCC) return;
    out_h[i] = hist[i] * GAMMA + (1.0f - GAMMA) * g_bhist[i];
}

// ---------------------------------------------------------------
extern "C" void kernel_launch(void* const* d_in, const int* in_sizes, int n_in,
                              void* d_out, int out_size) {
    const float* X    = (const float*)d_in[0];  // [B,D]
    const int*   keys = (const int*)  d_in[1];  // [B]
    const float* W    = (const float*)d_in[2];  // [D,K]
    const float* cs   = (const float*)d_in[3];  // [K]
    const float* ea   = (const float*)d_in[4];  // [D,K]
    const float* hist = (const float*)d_in[5];  // [K,C]

    float* out    = (float*)d_out;
    float* out_w  = out;                        // D*K
    float* out_cs = out + DK;                   // K
    float* out_ea = out + DK + KC;              // D*K
    float* out_h  = out + DK + KC + DK;         // K*C
    float* out_am = out + DK + KC + DK + KCC;   // B

    cudaFuncSetAttribute(argmin_mma, cudaFuncAttributeMaxDynamicSharedMemorySize,
                         SM_TOTAL);

    int total_zero = KC + KC * DIM + KC * NCLS;
    zero_kernel<<<(total_zero + 255) / 256, 256>>>();
    wsq_kernel<<<(KC + 255) / 256, 256>>>(W);
    wt_kernel<<<dim3(KC / 32, DIM / 32), dim3(32, 8)>>>(W);
    argmin_mma<<<BATCH / 128, 512, SM_TOTAL>>>(X, out_am);
    rescue_kernel<<<128, 128>>>(X, out_am);
    scatter_kernel<<<BATCH, 128>>>(X, keys);
    fincs_kernel<<<1, KC>>>(cs, out_cs);
    finw_kernel<<<dim3(KC / 32, DIM / 32), dim3(32, 8)>>>(ea, out_cs, out_w, out_ea);
    finh_kernel<<<(KCC + 255) / 256, 256>>>(hist, out_h);
}

// round 6
// speedup vs baseline: 1.0179x; 1.0179x over previous
#include <cuda_runtime.h>
#include <cuda_bf16.h>
#include <cstdint>
#include <float.h>

#define BATCH 65536
#define DIM   512
#define KC    1024
#define NCLS  100
#define GAMMA 0.99f
#define EPSV  1e-5f

#define DK (DIM * KC)      // 524288
#define KCC (KC * NCLS)    // 102400

// ---------------- scratch (device globals) ----------------
__device__ float                 g_wsq[KC];
__device__ float                 g_counts[KC];
__device__ __align__(16) float   g_esum[KC * DIM];     // [K][D]
__device__ float                 g_bhist[KC * NCLS];
__device__ int                   g_argmin[BATCH];
__device__ float                 g_n;
__device__ __align__(16) __nv_bfloat16 g_wbf[DIM * KC];  // bf16 W, [D][K]
__device__ float                 g_wt32[KC * DIM];     // W^T fp32 [K][D] (rescue)
__device__ int                   g_rescue_cnt;
__device__ int                   g_r_row[BATCH];
__device__ int                   g_r_k[BATCH * 4];

// ---------------- PTX helpers (sm_100-base safe) ----------------
__device__ __forceinline__ uint32_t smem_u32(const void* p) {
    uint32_t a;
    asm("{ .reg .u64 t; cvta.to.shared.u64 t, %1; cvt.u32.u64 %0, t; }"
        : "=r"(a) : "l"(p));
    return a;
}
__device__ __forceinline__ void ldsm_x4(uint32_t* r, uint32_t addr) {
    asm volatile("ldmatrix.sync.aligned.m8n8.x4.shared.b16 {%0,%1,%2,%3}, [%4];"
                 : "=r"(r[0]), "=r"(r[1]), "=r"(r[2]), "=r"(r[3]) : "r"(addr));
}
__device__ __forceinline__ void ldsm_x4_t(uint32_t* r, uint32_t addr) {
    asm volatile("ldmatrix.sync.aligned.m8n8.x4.trans.shared.b16 {%0,%1,%2,%3}, [%4];"
                 : "=r"(r[0]), "=r"(r[1]), "=r"(r[2]), "=r"(r[3]) : "r"(addr));
}
__device__ __forceinline__ void mma16816(float* c, const uint32_t* a,
                                         uint32_t b0, uint32_t b1) {
    asm volatile("mma.sync.aligned.m16n8k16.row.col.f32.bf16.bf16.f32 "
                 "{%0,%1,%2,%3}, {%4,%5,%6,%7}, {%8,%9}, {%0,%1,%2,%3};"
                 : "+f"(c[0]), "+f"(c[1]), "+f"(c[2]), "+f"(c[3])
                 : "r"(a[0]), "r"(a[1]), "r"(a[2]), "r"(a[3]), "r"(b0), "r"(b1));
}
__device__ __forceinline__ void cp_async16(uint32_t dst, const void* src) {
    asm volatile("cp.async.cg.shared.global [%0], [%1], 16;"
                 :: "r"(dst), "l"(src) : "memory");
}
#define CP_COMMIT() asm volatile("cp.async.commit_group;" ::: "memory")
#define CP_WAIT1()  asm volatile("cp.async.wait_group 1;"  ::: "memory")
__device__ __forceinline__ uint32_t bf2u(float lo, float hi) {
    __nv_bfloat162 p = __floats2bfloat162_rn(lo, hi);
    return *reinterpret_cast<uint32_t*>(&p);
}

// ---------------------------------------------------------------
__global__ void zero_kernel() {
    int total = KC + KC * DIM + KC * NCLS;
    for (int i = blockIdx.x * blockDim.x + threadIdx.x; i < total;
         i += gridDim.x * blockDim.x) {
        if (i < KC) g_counts[i] = 0.0f;
        else if (i < KC + KC * DIM) g_esum[i - KC] = 0.0f;
        else g_bhist[i - KC - KC * DIM] = 0.0f;
    }
    if (blockIdx.x == 0 && threadIdx.x == 0) g_rescue_cnt = 0;
}

__global__ void wsq_kernel(const float* __restrict__ W) {
    int k = blockIdx.x * blockDim.x + threadIdx.x;
    if (k >= KC) return;
    float a = 0.0f;
    #pragma unroll 8
    for (int d = 0; d < DIM; d++) {
        float w = W[d * KC + k];
        a += w * w;
    }
    g_wsq[k] = a;
}

// Transpose W [D][K] -> W^T fp32 [K][D] (rescue) + write bf16 copy [D][K]
__global__ void wt_kernel(const float* __restrict__ W) {
    __shared__ float tile[32][33];
    int k0 = blockIdx.x * 32, d0 = blockIdx.y * 32;
    int tx = threadIdx.x, ty = threadIdx.y;   // (32, 8)
    #pragma unroll
    for (int j = 0; j < 4; j++) {
        size_t gi = (size_t)(d0 + ty + 8 * j) * KC + k0 + tx;
        float v = W[gi];
        tile[ty + 8 * j][tx] = v;
        g_wbf[gi] = __float2bfloat16_rn(v);
    }
    __syncthreads();
    #pragma unroll
    for (int j = 0; j < 4; j++)
        g_wt32[(size_t)(k0 + ty + 8 * j) * DIM + d0 + tx] = tile[tx][ty + 8 * j];
}

// ---------------------------------------------------------------
// mma.sync bf16 GEMM + top-k argmin.
// 256 threads, 8 warps (2m x 4n), warp tile 64x64 -> 128 B smem per MMA.
// CTA: 128 rows x n-chunks of 256.  A resident (128KB); B chunk
// 64d x 256n = 32KB, 2-stage cp.async ring.
// ---------------------------------------------------------------
#define SA_OFF   0                     // 131072: A [128][512] bf16, row 1024B
#define SB_OFF   131072                // 2 x 32768 B ring, row 512B
#define WSQ_OFF  (SB_OFF + 65536)      // 196608, 4096 bytes
#define RED_OFF  SB_OFF                // reuse ring for merge: 128*16*16 = 32768
#define SM_TOTAL (WSQ_OFF + 4096)      // 200704
#define RESCUE_T 2.0f

__device__ __forceinline__ void load_b_chunk(uint32_t smb, int c, int tid) {
    int stage = c & 1;
    int d0 = (c & 7) * 64, n0 = (c >> 3) * 256;
    #pragma unroll
    for (int t = 0; t < 8; t++) {
        int ul = t * 256 + tid;          // 0..2047 16B units
        int kr = ul >> 5, u = ul & 31;
        cp_async16(smb + SB_OFF + stage * 32768 + kr * 512 + ((u ^ (kr & 7)) * 16),
                   &g_wbf[(size_t)(d0 + kr) * KC + n0 + u * 8]);
    }
}

__global__ __launch_bounds__(256, 1)
void argmin_mma(const float* __restrict__ X, float* __restrict__ out_am) {
    extern __shared__ unsigned char sm[];
    uint32_t smb = smem_u32(sm);
    float*  s_wsq = (float*)(sm + WSQ_OFF);
    float4* red   = (float4*)(sm + RED_OFF);

    int tid  = threadIdx.x;
    int lane = tid & 31;
    int wid  = tid >> 5;
    int wm   = wid >> 2;        // 0..1 -> rows wm*64..+64
    int wn   = wid & 3;         // 0..3 -> cols wn*64..+64
    int row0 = blockIdx.x * 128;

    #pragma unroll
    for (int i = tid; i < KC; i += 256) s_wsq[i] = g_wsq[i];

    // ---- load X tile -> bf16 swizzled smem (A resident) ----
    #pragma unroll
    for (int it = 0; it < 32; it++) {
        int ul = it * 256 + tid;        // 8192 16B units
        int r = ul >> 6, u = ul & 63;
        const float4* xp = reinterpret_cast<const float4*>(
            &X[(size_t)(row0 + r) * DIM + u * 8]);
        float4 f0 = xp[0], f1 = xp[1];
        uint4 q;
        q.x = bf2u(f0.x, f0.y); q.y = bf2u(f0.z, f0.w);
        q.z = bf2u(f1.x, f1.y); q.w = bf2u(f1.z, f1.w);
        *reinterpret_cast<uint4*>(sm + SA_OFF + r * 1024 + ((u ^ (r & 7)) * 16)) = q;
    }

    // prologue: stage 0
    load_b_chunk(smb, 0, tid); CP_COMMIT();

    float tv1[8], tv2[8];
    int   tk1[8], tk2[8];
    #pragma unroll
    for (int s = 0; s < 8; s++) { tv1[s] = FLT_MAX; tv2[s] = FLT_MAX; tk1[s] = KC; tk2[s] = KC; }

    int mx = lane & 7;          // A row & 7
    int hi = lane >> 4;
    int kl = lane & 15;
    int kx = kl & 7;

    for (int nc = 0; nc < 4; nc++) {
        float acc[4][8][4];
        #pragma unroll
        for (int i = 0; i < 4; i++)
            #pragma unroll
            for (int j = 0; j < 8; j++)
                #pragma unroll
                for (int c = 0; c < 4; c++) acc[i][j][c] = 0.0f;

        for (int dc = 0; dc < 8; dc++) {
            int c = nc * 8 + dc;
            if (c + 1 < 32) load_b_chunk(smb, c + 1, tid);
            CP_COMMIT();
            CP_WAIT1();                   // chunk c complete
            __syncthreads();              // visible CTA-wide
            uint32_t bbase = smb + SB_OFF + (c & 1) * 32768;
            #pragma unroll
            for (int ks = 0; ks < 4; ks++) {
                uint32_t a[4][4];
                #pragma unroll
                for (int i = 0; i < 4; i++) {
                    int row = wm * 64 + i * 16 + kl;
                    ldsm_x4(a[i], smb + SA_OFF + row * 1024 +
                                  (((dc * 8 + ks * 2 + hi) ^ mx) * 16));
                }
                uint32_t bfr[4][4];
                #pragma unroll
                for (int jj = 0; jj < 4; jj++)
                    ldsm_x4_t(bfr[jj], bbase + (ks * 16 + kl) * 512 +
                                       (((wn * 8 + jj * 2 + hi) ^ kx) * 16));
                #pragma unroll
                for (int i = 0; i < 4; i++)
                    #pragma unroll
                    for (int jj = 0; jj < 4; jj++) {
                        mma16816(acc[i][jj * 2],     a[i], bfr[jj][0], bfr[jj][1]);
                        mma16816(acc[i][jj * 2 + 1], a[i], bfr[jj][2], bfr[jj][3]);
                    }
            }
            __syncthreads();              // compute done before stage reuse
        }

        // ---- epilogue: scores + running top-2 per row-slot ----
        int kbase = nc * 256 + wn * 64 + (lane & 3) * 2;
        #pragma unroll
        for (int i = 0; i < 4; i++)
            #pragma unroll
            for (int h = 0; h < 2; h++) {
                int slot = i * 2 + h;
                #pragma unroll
                for (int j = 0; j < 8; j++) {
                    int kg = kbase + j * 8;
                    float s0 = fmaf(-2.0f, acc[i][j][h * 2 + 0], s_wsq[kg]);
                    float s1 = fmaf(-2.0f, acc[i][j][h * 2 + 1], s_wsq[kg + 1]);
                    if (s0 < tv1[slot])      { tv2[slot] = tv1[slot]; tk2[slot] = tk1[slot]; tv1[slot] = s0; tk1[slot] = kg; }
                    else if (s0 < tv2[slot]) { tv2[slot] = s0; tk2[slot] = kg; }
                    if (s1 < tv1[slot])      { tv2[slot] = tv1[slot]; tk2[slot] = tk1[slot]; tv1[slot] = s1; tk1[slot] = kg + 1; }
                    else if (s1 < tv2[slot]) { tv2[slot] = s1; tk2[slot] = kg + 1; }
                }
            }
    }

    // ---- per-thread top-2 -> merge smem (ring no longer needed) ----
    __syncthreads();
    int ci = wn * 4 + (lane & 3);
    #pragma unroll
    for (int slot = 0; slot < 8; slot++) {
        int i = slot >> 1, h = slot & 1;
        int r = wm * 64 + i * 16 + h * 8 + (lane >> 2);
        float4 e;
        e.x = tv1[slot]; e.y = __int_as_float(tk1[slot]);
        e.z = tv2[slot]; e.w = __int_as_float(tk2[slot]);
        red[r * 16 + ci] = e;
    }
    __syncthreads();

    // ---- per-row merge: top-4 of 32 candidates, lexicographic (v, k) ----
    if (tid < 128) {
        float bv[4] = {FLT_MAX, FLT_MAX, FLT_MAX, FLT_MAX};
        int   bk[4] = {KC, KC, KC, KC};
        #pragma unroll
        for (int c = 0; c < 16; c++) {
            float4 e = red[tid * 16 + c];
            float cv[2] = {e.x, e.z};
            int   ck[2] = {__float_as_int(e.y), __float_as_int(e.w)};
            #pragma unroll
            for (int w = 0; w < 2; w++) {
                float v = cv[w]; int k = ck[w];
                if (v < bv[3] || (v == bv[3] && k < bk[3])) {
                    bv[3] = v; bk[3] = k;
                    if (bv[3] < bv[2] || (bv[3] == bv[2] && bk[3] < bk[2])) {
                        float t = bv[2]; bv[2] = bv[3]; bv[3] = t;
                        int ti = bk[2]; bk[2] = bk[3]; bk[3] = ti;
                    }
                    if (bv[2] < bv[1] || (bv[2] == bv[1] && bk[2] < bk[1])) {
                        float t = bv[1]; bv[1] = bv[2]; bv[2] = t;
                        int ti = bk[1]; bk[1] = bk[2]; bk[2] = ti;
                    }
                    if (bv[1] < bv[0] || (bv[1] == bv[0] && bk[1] < bk[0])) {
                        float t = bv[0]; bv[0] = bv[1]; bv[1] = t;
                        int ti = bk[0]; bk[0] = bk[1]; bk[1] = ti;
                    }
                }
            }
        }
        int b = row0 + tid;
        if (bv[1] - bv[0] > RESCUE_T) {
            g_argmin[b] = bk[0];
            out_am[b] = (float)bk[0];
        } else {
            int e = atomicAdd(&g_rescue_cnt, 1);
            g_r_row[e] = b;
            #pragma unroll
            for (int w = 0; w < 4; w++) g_r_k[e * 4 + w] = bk[w];
        }
    }
}

// ---------------------------------------------------------------
// Exact fp32 rescue: top-4 candidates per flagged row, one warp each.
// ---------------------------------------------------------------
__global__ void rescue_kernel(const float* __restrict__ X,
                              float* __restrict__ out_am) {
    int lane = threadIdx.x & 31;
    int warpGlobal = (blockIdx.x * blockDim.x + threadIdx.x) >> 5;
    int nWarps = (gridDim.x * blockDim.x) >> 5;
    int cnt = g_rescue_cnt;
    for (int e = warpGlobal; e < cnt; e += nWarps) {
        int b = g_r_row[e];
        int kk[4];
        #pragma unroll
        for (int w = 0; w < 4; w++) kk[w] = g_r_k[e * 4 + w];
        const float* xr = X + (size_t)b * DIM;
        float dot[4] = {0.0f, 0.0f, 0.0f, 0.0f};
        #pragma unroll 4
        for (int d = lane; d < DIM; d += 32) {
            float x = xr[d];
            #pragma unroll
            for (int w = 0; w < 4; w++)
                if (kk[w] < KC)
                    dot[w] += x * g_wt32[(size_t)kk[w] * DIM + d];
        }
        #pragma unroll
        for (int off = 16; off > 0; off >>= 1)
            #pragma unroll
            for (int w = 0; w < 4; w++)
                dot[w] += __shfl_xor_sync(0xffffffff, dot[w], off);
        if (lane == 0) {
            float bv = FLT_MAX; int bi = KC;
            #pragma unroll
            for (int w = 0; w < 4; w++) {
                if (kk[w] >= KC) continue;
                float s = g_wsq[kk[w]] - 2.0f * dot[w];
                if (s < bv || (s == bv && kk[w] < bi)) { bv = s; bi = kk[w]; }
            }
            g_argmin[b] = bi;
            out_am[b] = (float)bi;
        }
    }
}

// ---------------------------------------------------------------
// Scatter: warp per row, vector red.global.add.v4 (coalesced)
// ---------------------------------------------------------------
__global__ void scatter_kernel(const float* __restrict__ X,
                               const int* __restrict__ keys) {
    int warp = threadIdx.x >> 5;
    int lane = threadIdx.x & 31;
    int b = blockIdx.x * 8 + warp;
    int k = g_argmin[b];
    if (lane == 0) {
        atomicAdd(&g_counts[k], 1.0f);
        atomicAdd(&g_bhist[k * NCLS + keys[b]], 1.0f);
    }
    const float* xr = X + (size_t)b * DIM;
    float* es = g_esum + (size_t)k * DIM;
    #pragma unroll
    for (int i = 0; i < 4; i++) {
        int d = (lane + i * 32) * 4;
        float4 v = *reinterpret_cast<const float4*>(xr + d);
        asm volatile("red.global.add.v4.f32 [%0], {%1, %2, %3, %4};"
                     :: "l"(es + d), "f"(v.x), "f"(v.y), "f"(v.z), "f"(v.w) : "memory");
    }
}

__global__ void fincs_kernel(const float* __restrict__ cs,
                             float* __restrict__ out_cs) {
    __shared__ float sred[KC];
    int k = threadIdx.x;
    float c = g_counts[k];
    if (c == 0.0f) c = 1.0f;
    float ncs = cs[k] * GAMMA + (1.0f - GAMMA) * c;
    out_cs[k] = ncs;
    sred[k] = ncs;
    __syncthreads();
    for (int s = KC / 2; s > 0; s >>= 1) {
        if (k < s) sred[k] += sred[k + s];
        __syncthreads();
    }
    if (k == 0) g_n = sred[0];
}

// finalize weight + embed_avg: tiled transpose of g_esum for coalescing
__global__ void finw_kernel(const float* __restrict__ ea,
                            const float* __restrict__ out_cs,
                            float* __restrict__ out_w,
                            float* __restrict__ out_ea) {
    __shared__ float tile[32][33];
    int k0 = blockIdx.x * 32, d0 = blockIdx.y * 32;
    int tx = threadIdx.x, ty = threadIdx.y;   // (32, 8)
    #pragma unroll
    for (int j = 0; j < 4; j++)
        tile[ty + 8 * j][tx] = g_esum[(size_t)(k0 + ty + 8 * j) * DIM + d0 + tx];
    __syncthreads();
    float n = g_n;
    float csn = (out_cs[k0 + tx] + EPSV) / (n + KC * EPSV) * n;
    #pragma unroll
    for (int j = 0; j < 4; j++) {
        size_t i = (size_t)(d0 + ty + 8 * j) * KC + k0 + tx;
        float e = ea[i] * GAMMA + (1.0f - GAMMA) * tile[tx][ty + 8 * j];
        out_ea[i] = e;
        out_w[i] = e / csn;
    }
}

__global__ void finh_kernel(const float* __restrict__ hist,
                            float* __restrict__ out_h) {
    int i = blockIdx.x * blockDim.x + threadIdx.x;
    if (i >= KCC) return;
    out_h[i] = hist[i] * GAMMA + (1.0f - GAMMA) * g_bhist[i];
}

// ---------------------------------------------------------------
extern "C" void kernel_launch(void* const* d_in, const int* in_sizes, int n_in,
                              void* d_out, int out_size) {
    const float* X    = (const float*)d_in[0];  // [B,D]
    const int*   keys = (const int*)  d_in[1];  // [B]
    const float* W    = (const float*)d_in[2];  // [D,K]
    const float* cs   = (const float*)d_in[3];  // [K]
    const float* ea   = (const float*)d_in[4];  // [D,K]
    const float* hist = (const float*)d_in[5];  // [K,C]

    float* out    = (float*)d_out;
    float* out_w  = out;                        // D*K
    float* out_cs = out + DK;                   // K
    float* out_ea = out + DK + KC;              // D*K
    float* out_h  = out + DK + KC + DK;         // K*C
    float* out_am = out + DK + KC + DK + KCC;   // B

    cudaFuncSetAttribute(argmin_mma, cudaFuncAttributeMaxDynamicSharedMemorySize,
                         SM_TOTAL);

    int total_zero = KC + KC * DIM + KC * NCLS;
    zero_kernel<<<(total_zero + 255) / 256, 256>>>();
    wsq_kernel<<<(KC + 255) / 256, 256>>>(W);
    wt_kernel<<<dim3(KC / 32, DIM / 32), dim3(32, 8)>>>(W);
    argmin_mma<<<BATCH / 128, 256, SM_TOTAL>>>(X, out_am);
    rescue_kernel<<<128, 128>>>(X, out_am);
    scatter_kernel<<<BATCH / 8, 256>>>(X, keys);
    fincs_kernel<<<1, KC>>>(cs, out_cs);
    finw_kernel<<<dim3(KC / 32, DIM / 32), dim3(32, 8)>>>(ea, out_cs, out_w, out_ea);
    finh_kernel<<<(KCC + 255) / 256, 256>>>(hist, out_h);
}